// round 10
// baseline (speedup 1.0000x reference)
#include <cuda_runtime.h>

// RegionPartitioner, band-aligned one-load/four-store, 32B-per-thread variant.
// out[b, r, c, i, j] = x[b, c, min(ri*32+i, 499), min(rj*32+j, 499)],
//   r = ri*15 + rj, 15x15 regions of 64x64, step 32.
// Output: (8, 225, 4, 64, 64) fp32.
//
// Each thread owns an 8-float (32B) chunk of one 32x32 input band, loads it
// as two independent float4 (MLP=2), and stores it to its <=2x2 region
// positions (4 base addresses, 8 STG.128 total). Every output element is
// written exactly once; edge replication handled by load-time clamping.

namespace {
constexpr int B  = 8;
constexpr int C  = 4;
constexpr int H  = 500;
constexpr int W  = 500;
constexpr int RS = 64;
constexpr int NR = 15;
constexpr int R  = NR * NR;     // 225
}  // namespace

__global__ __launch_bounds__(256)
void region_partition_kernel(const float* __restrict__ x,
                             float4* __restrict__ out) {
    const int blk = blockIdx.x;          // 0..127
    const int rb  = blk >> 3;            // row band 0..15
    const int cbp = blk & 7;             // column band pair 0..7
    const int bc  = blockIdx.y;          // 0..31
    const int b   = bc >> 2;
    const int c   = bc & 3;

    const int t  = threadIdx.x;          // 0..255
    const int tr = t >> 3;               // row within band 0..31
    const int g  = t & 7;                // 8-float group within 64-col span
    const int cb = (cbp << 1) | (g >> 2);   // column band 0..15
    const int tg = g & 3;                // 8-float group within 32-col band

    // ---- Load this thread's 32B input chunk once (clamped at edges). ----
    const int row  = min(rb * 32 + tr, H - 1);
    const int col0 = cb * 32 + tg * 8;
    const float* src = x + ((long long)bc * H + row) * W;

    float4 v0, v1;
    if (col0 + 7 <= W - 1) {
        v0 = *reinterpret_cast<const float4*>(src + col0);
        v1 = *reinterpret_cast<const float4*>(src + col0 + 4);
    } else {                             // cb==15, tg>=2 only: cols >= 500
        v0.x = src[min(col0,     W - 1)];
        v0.y = src[min(col0 + 1, W - 1)];
        v0.z = src[min(col0 + 2, W - 1)];
        v0.w = src[min(col0 + 3, W - 1)];
        v1.x = src[min(col0 + 4, W - 1)];
        v1.y = src[min(col0 + 5, W - 1)];
        v1.z = src[min(col0 + 6, W - 1)];
        v1.w = src[min(col0 + 7, W - 1)];
    }

    // ---- Target regions (block/quad-uniform branches). ----
    int ris[2], iis[2], nri = 0;
    if (rb >= 1)      { ris[nri] = rb - 1; iis[nri] = 32 + tr; nri++; }
    if (rb <= NR - 1) { ris[nri] = rb;     iis[nri] = tr;      nri++; }
    int rjs[2], jjs[2], nrj = 0;
    if (cb >= 1)      { rjs[nrj] = cb - 1; jjs[nrj] = 8 + 2 * tg; nrj++; }
    if (cb <= NR - 1) { rjs[nrj] = cb;     jjs[nrj] = 2 * tg;     nrj++; }

    // Stores: per destination, one base address + two adjacent float4 writes.
    // For fixed (a,d,row) a g-quad writes a contiguous 128B run.
#pragma unroll
    for (int a = 0; a < 2; a++) {
        if (a >= nri) break;
#pragma unroll
        for (int d = 0; d < 2; d++) {
            if (d >= nrj) break;
            float4* dst = out +
                (((long long)(b * R + ris[a] * NR + rjs[d]) * C + c) * RS +
                 iis[a]) * (RS / 4) + jjs[d];
            dst[0] = v0;
            dst[1] = v1;
        }
    }
}

extern "C" void kernel_launch(void* const* d_in, const int* in_sizes, int n_in,
                              void* d_out, int out_size) {
    const float* x = (const float*)d_in[0];
    float4* out = (float4*)d_out;

    dim3 grid(16 * 8, B * C);   // (128, 32) = 4096 blocks, 1.05M threads
    region_partition_kernel<<<grid, 256>>>(x, out);
}

// round 11
// speedup vs baseline: 1.0870x; 1.0870x over previous
#include <cuda_runtime.h>

// RegionPartitioner, band-aligned write-once, 2-rows-per-thread variant.
// out[b, r, c, i, j] = x[b, c, min(ri*32+i, 499), min(rj*32+j, 499)],
//   r = ri*15 + rj, 15x15 regions of 64x64, step 32.
// Output: (8, 225, 4, 64, 64) fp32.
//
// One thread owns a 16B column-chunk of TWO rows (tr, tr+16) of one 32x32
// input band. Both rows map to the same <=2x2 region set, so the 4 region
// base addresses are computed once; the second row's stores reuse them with
// a constant +256 float4 offset. 2 LDG.128 (independent) + 8 STG.128/thread.
// Every output element written exactly once; edge replication via load-time
// clamping. Block = 2 row-bands, warp-aligned halves (no warp divergence).

namespace {
constexpr int B  = 8;
constexpr int C  = 4;
constexpr int H  = 500;
constexpr int W  = 500;
constexpr int RS = 64;
constexpr int NR = 15;
constexpr int R  = NR * NR;     // 225
}  // namespace

__global__ __launch_bounds__(256)
void region_partition_kernel(const float* __restrict__ x,
                             float4* __restrict__ out) {
    const int blk = blockIdx.x;            // 0..127
    const int rbp = blk >> 4;              // row-band pair 0..7
    const int cb  = blk & 15;              // col band 0..15
    const int bc  = blockIdx.y;            // 0..31
    const int b   = bc >> 2;
    const int c   = bc & 3;

    const int t   = threadIdx.x;           // 0..255
    const int rb  = (rbp << 1) | (t >> 7); // row band; warp-uniform (half split)
    const int th  = t & 127;               // thread within band-half
    const int tc  = th & 7;                // 16B column chunk (8 x 16B = 32 cols)
    const int tr  = th >> 3;               // 0..15 -> rows tr and tr+16

    // ---- Load two rows of this thread's 16B chunk (clamped at edges). ----
    const int row0 = rb * 32 + tr;              // <= 495+15 = 493 for rb<=15? rb=15: 480+15=495 -> fine
    const int row1 = min(row0 + 16, H - 1);     // rb==15, tr>=4 clamps to 499
    const int rA   = min(row0, H - 1);
    const int col0 = cb * 32 + tc * 4;
    const float* srcb = x + (long long)bc * H * W;
    const float* p0 = srcb + rA   * W;
    const float* p1 = srcb + row1 * W;

    float4 v0, v1;
    if (col0 + 3 <= W - 1) {
        v0 = *reinterpret_cast<const float4*>(p0 + col0);
        v1 = *reinterpret_cast<const float4*>(p1 + col0);
    } else {                               // cb==15, tc>=5: cols >= 500
        const int c0 = min(col0,     W - 1);
        const int c1 = min(col0 + 1, W - 1);
        const int c2 = min(col0 + 2, W - 1);
        const int c3 = min(col0 + 3, W - 1);
        v0.x = p0[c0]; v0.y = p0[c1]; v0.z = p0[c2]; v0.w = p0[c3];
        v1.x = p1[c0]; v1.y = p1[c1]; v1.z = p1[c2]; v1.w = p1[c3];
    }

    // ---- Target regions (warp-uniform branches). ----
    int ris[2], iis[2], nri = 0;
    if (rb >= 1)      { ris[nri] = rb - 1; iis[nri] = 32 + tr; nri++; }
    if (rb <= NR - 1) { ris[nri] = rb;     iis[nri] = tr;      nri++; }
    int rjs[2], jjs[2], nrj = 0;
    if (cb >= 1)      { rjs[nrj] = cb - 1; jjs[nrj] = 8 + tc;  nrj++; }
    if (cb <= NR - 1) { rjs[nrj] = cb;     jjs[nrj] = tc;      nrj++; }

    // Stores: per (a,d), one base address; row tr -> base, row tr+16 -> base+256.
    // For fixed (a,d,row), 8 consecutive tc write a contiguous 128B run.
#pragma unroll
    for (int a = 0; a < 2; a++) {
        if (a >= nri) break;
#pragma unroll
        for (int d = 0; d < 2; d++) {
            if (d >= nrj) break;
            float4* dst = out +
                (((long long)(b * R + ris[a] * NR + rjs[d]) * C + c) * RS +
                 iis[a]) * (RS / 4) + jjs[d];
            dst[0]       = v0;
            dst[16 * 16] = v1;            // +16 region rows = +256 float4
        }
    }
}

extern "C" void kernel_launch(void* const* d_in, const int* in_sizes, int n_in,
                              void* d_out, int out_size) {
    const float* x = (const float*)d_in[0];
    float4* out = (float4*)d_out;

    dim3 grid(8 * 16, B * C);   // (128, 32) = 4096 blocks, 1.05M threads
    region_partition_kernel<<<grid, 256>>>(x, out);
}